// round 15
// baseline (speedup 1.0000x reference)
#include <cuda_runtime.h>
#include <cuda_fp16.h>
#include <cstdint>

#define NN 100000
#define EE 1600000
#define FIN 256
#define HID 128
#define NCLS 40
#define NB_SCAN 98   // ceil(NN/1024)
#define AGG_CHUNK 4
#define AGG_BLOCKS 1024

// ---------------- scratch (device globals; no allocation allowed) ----------------
__device__ float  g_csrc[NN];
__device__ float  g_cdst[NN];
__device__ int    g_cnt_s[NN];
__device__ int    g_cnt_d[NN];
__device__ int    g_rowptr[NN + 1];
__device__ int    g_pos[NN];
__device__ int    g_bsum[128];
__device__ int    g_tick[2];                  // work-stealing tickets (agg0, agg1)
__device__ int    g_esrc[EE];
__device__ __half g_half[(size_t)NN * HID];   // fp16 h (gather-side, layer outputs)
__device__ __half g_h1[(size_t)NN * HID];     // fp16 h1 (layer-0 agg out = GEMM-1 in)

// ---------------- mma.sync tf32 helpers (baseline PTX, compiles at compute_103) ---
__device__ __forceinline__ uint32_t f2tf32(float x) {
    uint32_t r;
    asm("cvt.rna.tf32.f32 %0, %1;" : "=r"(r) : "f"(x));
    return r;
}
__device__ __forceinline__ void mma_tf32(float* d, const uint32_t* a, const uint32_t* b) {
    asm volatile(
        "mma.sync.aligned.m16n8k8.row.col.f32.tf32.tf32.f32 "
        "{%0,%1,%2,%3}, {%4,%5,%6,%7}, {%8,%9}, {%0,%1,%2,%3};"
        : "+f"(d[0]), "+f"(d[1]), "+f"(d[2]), "+f"(d[3])
        : "r"(a[0]), "r"(a[1]), "r"(a[2]), "r"(a[3]), "r"(b[0]), "r"(b[1]));
}

// ============ HMMA tf32 GEMM: out[r][c] = (A[r][:] @ W[:][c]) * rowscale[r] ========
// CTA tile 128x128; 8 warps (2x4); warp tile 64x32; K chunked by 32.
// A chunk register-prefetched (next chunk's loads overlap current chunk's mma).
template <int K_DIM, bool HALF_IN, bool HALF_OUT>
__global__ void __launch_bounds__(256, 2) mma_gemm_kernel(
    const void* __restrict__ A_v, const float* __restrict__ W,
    const float* __restrict__ rowscale, void* __restrict__ out_v, int n) {
    __shared__ uint32_t sA[128][36];
    __shared__ uint32_t sW[32][136];

    const int t = threadIdx.x;
    const int wid = t >> 5;
    const int lane = t & 31;
    const int g = lane >> 2;      // 0..7
    const int l4 = lane & 3;      // 0..3
    const int warpM = wid >> 2;   // 0..1
    const int warpN = wid & 3;    // 0..3
    const int row0 = blockIdx.x * 128;

    // per-thread A-load coordinates (4 vectors of 4 elems)
    int arow[4], akq[4];
#pragma unroll
    for (int i = 0; i < 4; i++) {
        int j4 = t + i * 256;
        arow[i] = j4 >> 3;
        akq[i] = j4 & 7;
    }

    float acc[4][4][4];
#pragma unroll
    for (int mi = 0; mi < 4; mi++)
#pragma unroll
        for (int nj = 0; nj < 4; nj++)
#pragma unroll
            for (int r = 0; r < 4; r++) acc[mi][nj][r] = 0.f;

    // prefetch chunk 0 of A into registers
    float4 pfA[4];
#pragma unroll
    for (int i = 0; i < 4; i++) {
        int grow = row0 + arow[i];
        float4 v = make_float4(0.f, 0.f, 0.f, 0.f);
        if (grow < n) {
            if (HALF_IN) {
                const __half* Ah = (const __half*)A_v;
                int2 p = *reinterpret_cast<const int2*>(Ah + (size_t)grow * K_DIM + akq[i] * 4);
                float2 f0 = __half22float2(*reinterpret_cast<__half2*>(&p.x));
                float2 f1 = __half22float2(*reinterpret_cast<__half2*>(&p.y));
                v = make_float4(f0.x, f0.y, f1.x, f1.y);
            } else {
                const float* Af = (const float*)A_v;
                v = *reinterpret_cast<const float4*>(Af + (size_t)grow * K_DIM + akq[i] * 4);
            }
        }
        pfA[i] = v;
    }

    const int NCH = K_DIM / 32;
    for (int ch = 0; ch < NCH; ch++) {
        const int k0 = ch * 32;
        // ---- commit prefetched A chunk to smem (tf32) ----
#pragma unroll
        for (int i = 0; i < 4; i++) {
            float4 v = pfA[i];
            uint4 b = make_uint4(f2tf32(v.x), f2tf32(v.y), f2tf32(v.z), f2tf32(v.w));
            *reinterpret_cast<uint4*>(&sA[arow[i]][akq[i] * 4]) = b;
        }
        // ---- stage W chunk (synchronous; L2-resident after first wave) ----
#pragma unroll
        for (int i = 0; i < 4; i++) {
            int j4 = t + i * 256;
            int kk = j4 >> 5, c4 = j4 & 31;
            float4 v = *reinterpret_cast<const float4*>(W + (size_t)(k0 + kk) * 128 + c4 * 4);
            uint4 b = make_uint4(f2tf32(v.x), f2tf32(v.y), f2tf32(v.z), f2tf32(v.w));
            *reinterpret_cast<uint4*>(&sW[kk][c4 * 4]) = b;
        }
        __syncthreads();
        // ---- issue next A chunk's loads (overlap with mma below) ----
        if (ch + 1 < NCH) {
            const int kn = k0 + 32;
#pragma unroll
            for (int i = 0; i < 4; i++) {
                int grow = row0 + arow[i];
                float4 v = make_float4(0.f, 0.f, 0.f, 0.f);
                if (grow < n) {
                    if (HALF_IN) {
                        const __half* Ah = (const __half*)A_v;
                        int2 p = *reinterpret_cast<const int2*>(Ah + (size_t)grow * K_DIM + kn + akq[i] * 4);
                        float2 f0 = __half22float2(*reinterpret_cast<__half2*>(&p.x));
                        float2 f1 = __half22float2(*reinterpret_cast<__half2*>(&p.y));
                        v = make_float4(f0.x, f0.y, f1.x, f1.y);
                    } else {
                        const float* Af = (const float*)A_v;
                        v = *reinterpret_cast<const float4*>(Af + (size_t)grow * K_DIM + kn + akq[i] * 4);
                    }
                }
                pfA[i] = v;
            }
        }
        // ---- 4 k8 steps ----
#pragma unroll
        for (int ks = 0; ks < 4; ks++) {
            const int k = ks * 8;
            uint32_t af[4][4], bf[4][2];
#pragma unroll
            for (int mi = 0; mi < 4; mi++) {
                int m = warpM * 64 + mi * 16 + g;
                af[mi][0] = sA[m][k + l4];
                af[mi][1] = sA[m + 8][k + l4];
                af[mi][2] = sA[m][k + l4 + 4];
                af[mi][3] = sA[m + 8][k + l4 + 4];
            }
#pragma unroll
            for (int nj = 0; nj < 4; nj++) {
                int nb = warpN * 32 + nj * 8 + g;
                bf[nj][0] = sW[k + l4][nb];
                bf[nj][1] = sW[k + l4 + 4][nb];
            }
#pragma unroll
            for (int mi = 0; mi < 4; mi++)
#pragma unroll
                for (int nj = 0; nj < 4; nj++)
                    mma_tf32(acc[mi][nj], af[mi], bf[nj]);
        }
        __syncthreads();
    }

    // ---- epilogue: scale rows, store ----
#pragma unroll
    for (int mi = 0; mi < 4; mi++) {
        int ra = row0 + warpM * 64 + mi * 16 + g;
        int rb = ra + 8;
        float sa = (ra < n) ? rowscale[ra] : 0.f;
        float sb = (rb < n) ? rowscale[rb] : 0.f;
#pragma unroll
        for (int nj = 0; nj < 4; nj++) {
            int col = warpN * 32 + nj * 8 + 2 * l4;
            if (HALF_OUT) {
                __half* o = (__half*)out_v;
                if (ra < n)
                    *reinterpret_cast<__half2*>(o + (size_t)ra * 128 + col) =
                        __floats2half2_rn(acc[mi][nj][0] * sa, acc[mi][nj][1] * sa);
                if (rb < n)
                    *reinterpret_cast<__half2*>(o + (size_t)rb * 128 + col) =
                        __floats2half2_rn(acc[mi][nj][2] * sb, acc[mi][nj][3] * sb);
            } else {
                float* o = (float*)out_v;
                if (ra < n) {
                    float2 v = make_float2(acc[mi][nj][0] * sa, acc[mi][nj][1] * sa);
                    *reinterpret_cast<float2*>(o + (size_t)ra * 128 + col) = v;
                }
                if (rb < n) {
                    float2 v = make_float2(acc[mi][nj][2] * sb, acc[mi][nj][3] * sb);
                    *reinterpret_cast<float2*>(o + (size_t)rb * 128 + col) = v;
                }
            }
        }
    }
}

// ---------------- zero counters + two int arrays in one launch ----------------
__global__ void zeroi2_kernel(int* __restrict__ p0, int* __restrict__ p1,
                              int* __restrict__ tick, int n) {
    int i = blockIdx.x * blockDim.x + threadIdx.x;
    if (i < n) { p0[i] = 0; p1[i] = 0; }
    if (i < 2) tick[i] = 0;
}

// ---------------- degree histogram (int) ----------------
__global__ void deg_kernel(const int* __restrict__ src, const int* __restrict__ dst,
                           int* __restrict__ cs, int* __restrict__ cd, int e) {
    int i = blockIdx.x * blockDim.x + threadIdx.x;
    if (i < e) {
        atomicAdd(&cs[src[i]], 1);
        atomicAdd(&cd[dst[i]], 1);
    }
}

// ---------------- scan stage 1 ----------------
__global__ void __launch_bounds__(256) scan_local_kernel(
    const int* __restrict__ in, int* __restrict__ out, int* __restrict__ bsum, int n) {
    __shared__ int wsum[8];
    int t = threadIdx.x;
    int base = blockIdx.x * 1024 + t * 4;
    int v[4];
#pragma unroll
    for (int i = 0; i < 4; i++) v[i] = (base + i < n) ? in[base + i] : 0;
    int tsum = v[0] + v[1] + v[2] + v[3];
    int lane = t & 31, wid = t >> 5;
    int inc = tsum;
#pragma unroll
    for (int off = 1; off < 32; off <<= 1) {
        int tmp = __shfl_up_sync(0xffffffffu, inc, off);
        if (lane >= off) inc += tmp;
    }
    if (lane == 31) wsum[wid] = inc;
    __syncthreads();
    if (t < 8) {
        int ws = wsum[t];
#pragma unroll
        for (int off = 1; off < 8; off <<= 1) {
            int tmp = __shfl_up_sync(0xffu, ws, off);
            if (t >= off) ws += tmp;
        }
        wsum[t] = ws;
    }
    __syncthreads();
    int excl = inc - tsum + (wid > 0 ? wsum[wid - 1] : 0);
    int run = excl;
#pragma unroll
    for (int i = 0; i < 4; i++) {
        if (base + i < n) out[base + i] = run;
        run += v[i];
    }
    if (t == 255) bsum[blockIdx.x] = wsum[7];
}

// ---------------- scan stage 2 ----------------
__global__ void scan_bsum_kernel(int* __restrict__ bsum, int nb) {
    __shared__ int s[128];
    int t = threadIdx.x;
    int v = (t < nb) ? bsum[t] : 0;
    s[t] = v;
    __syncthreads();
    for (int off = 1; off < 128; off <<= 1) {
        int tmp = (t >= off) ? s[t - off] : 0;
        __syncthreads();
        s[t] += tmp;
        __syncthreads();
    }
    if (t < nb) bsum[t] = s[t] - v;
}

// ------- scan stage 3 + degree norms fused ----------------
__global__ void scan_add_norm_kernel(int* __restrict__ rowptr, int* __restrict__ pos,
                                     const int* __restrict__ bsum,
                                     const int* __restrict__ cs, const int* __restrict__ cd,
                                     float* __restrict__ ncs, float* __restrict__ ncd, int n) {
    int i = blockIdx.x * blockDim.x + threadIdx.x;
    if (i < n) {
        int v = rowptr[i] + bsum[i >> 10];
        rowptr[i] = v;
        pos[i] = v;
        ncs[i] = rsqrtf(fmaxf((float)cs[i], 1.f));
        ncd[i] = rsqrtf(fmaxf((float)cd[i], 1.f));
    }
    if (i == 0) rowptr[n] = EE;
}

// ---------------- CSR bucket fill ----------------
__global__ void fill_kernel(const int* __restrict__ src, const int* __restrict__ dst,
                            int* __restrict__ pos, int* __restrict__ esrc, int e) {
    int i = blockIdx.x * blockDim.x + threadIdx.x;
    if (i < e) {
        int p = atomicAdd(&pos[dst[i]], 1);
        esrc[p] = src[i];
    }
}

// ------- aggregation v5: work-stealing warps, int2/lane gathers, MLP=8 -------------
// warp pops AGG_CHUNK dsts per ticket; per-dst result identical regardless of
// which warp processes it -> deterministic.
template <bool RELU, bool HALF_OUT>
__global__ void __launch_bounds__(256) agg_half_kernel(
    const __half* __restrict__ h, const int* __restrict__ esrc,
    const int* __restrict__ rowptr, const float* __restrict__ cdst,
    const float* __restrict__ bias, void* __restrict__ out_v,
    int* __restrict__ tick, int n) {
    const int lane = threadIdx.x & 31;
    const int2* hb = reinterpret_cast<const int2*>(h);  // 1 int2 = 4 halfs; 32/row
    const float4 b = ((const float4*)bias)[lane];

    for (;;) {
        int t0;
        if (lane == 0) t0 = atomicAdd(tick, 1);
        t0 = __shfl_sync(0xffffffffu, t0, 0);
        int base = t0 * AGG_CHUNK;
        if (base >= n) return;
        int wend = min(base + AGG_CHUNK, n);
        for (int w = base; w < wend; w++) {
            int beg = rowptr[w];
            int end = rowptr[w + 1];
            float4 acc = make_float4(0.f, 0.f, 0.f, 0.f);
            int e = beg;
            for (; e + 8 <= end; e += 8) {
                int s[8];
#pragma unroll
                for (int q = 0; q < 8; q++) s[q] = __ldg(&esrc[e + q]);
                int2 r[8];
#pragma unroll
                for (int q = 0; q < 8; q++) r[q] = __ldg(&hb[(size_t)s[q] * 32 + lane]);
#pragma unroll
                for (int q = 0; q < 8; q++) {
                    float2 a0 = __half22float2(*reinterpret_cast<__half2*>(&r[q].x));
                    float2 b0 = __half22float2(*reinterpret_cast<__half2*>(&r[q].y));
                    acc.x += a0.x; acc.y += a0.y; acc.z += b0.x; acc.w += b0.y;
                }
            }
            for (; e < end; e++) {
                int s = __ldg(&esrc[e]);
                int2 r0 = __ldg(&hb[(size_t)s * 32 + lane]);
                float2 a0 = __half22float2(*reinterpret_cast<__half2*>(&r0.x));
                float2 b0 = __half22float2(*reinterpret_cast<__half2*>(&r0.y));
                acc.x += a0.x; acc.y += a0.y; acc.z += b0.x; acc.w += b0.y;
            }
            float c = cdst[w];
            float4 r = make_float4(acc.x * c + b.x, acc.y * c + b.y,
                                   acc.z * c + b.z, acc.w * c + b.w);
            if (RELU) {
                r.x = fmaxf(r.x, 0.f); r.y = fmaxf(r.y, 0.f);
                r.z = fmaxf(r.z, 0.f); r.w = fmaxf(r.w, 0.f);
            }
            if (HALF_OUT) {
                __half2 h0 = __floats2half2_rn(r.x, r.y);
                __half2 h1 = __floats2half2_rn(r.z, r.w);
                int2 pk;
                pk.x = *reinterpret_cast<int*>(&h0);
                pk.y = *reinterpret_cast<int*>(&h1);
                reinterpret_cast<int2*>(out_v)[(size_t)w * 32 + lane] = pk;
            } else {
                reinterpret_cast<float4*>(out_v)[(size_t)w * 32 + lane] = r;
            }
        }
    }
}

// ---------------- classifier: logits = relu(h) @ Wc + bc ---------------------------
__global__ void __launch_bounds__(320) classifier_kernel(
    const float* __restrict__ h, const float* __restrict__ Wc,
    const float* __restrict__ bc, float* __restrict__ out, int n) {
    __shared__ float Wt[NCLS][132];   // [c][k]
    __shared__ float4 hs4[8][33];     // [r][k4], relu-applied
    __shared__ float bs[NCLS];

    const int t = threadIdx.x;
    for (int j = t; j < 128 * NCLS; j += 320) {
        int k = j / NCLS, c = j % NCLS;
        Wt[c][k] = Wc[j];
    }
    if (t < NCLS) bs[t] = bc[t];

    const int row0 = blockIdx.x * 64;
    const int r = t / NCLS;       // 0..7
    const int c = t % NCLS;       // 0..39
    for (int rr0 = 0; rr0 < 64; rr0 += 8) {
        __syncthreads();
        if (t < 256) {
            int lr = t >> 5, k4 = t & 31;
            int grow = row0 + rr0 + lr;
            float4 v = make_float4(0.f, 0.f, 0.f, 0.f);
            if (grow < n) {
                v = *reinterpret_cast<const float4*>(h + (size_t)grow * 128 + k4 * 4);
                v.x = fmaxf(v.x, 0.f); v.y = fmaxf(v.y, 0.f);
                v.z = fmaxf(v.z, 0.f); v.w = fmaxf(v.w, 0.f);
            }
            hs4[lr][k4] = v;
        }
        __syncthreads();
        float acc = bs[c];
#pragma unroll
        for (int k4 = 0; k4 < 32; k4++) {
            float4 hv = hs4[r][k4];
            float4 wv = *reinterpret_cast<const float4*>(&Wt[c][k4 * 4]);
            acc = fmaf(hv.x, wv.x, acc);
            acc = fmaf(hv.y, wv.y, acc);
            acc = fmaf(hv.z, wv.z, acc);
            acc = fmaf(hv.w, wv.w, acc);
        }
        int grow = row0 + rr0 + r;
        if (grow < n) out[(size_t)grow * NCLS + c] = acc;
    }
}

// ---------------- launch ------------------------------------------------------------
extern "C" void kernel_launch(void* const* d_in, const int* in_sizes, int n_in,
                              void* d_out, int out_size) {
    const float* x   = (const float*)d_in[0];
    const int*   src = (const int*)d_in[1];
    const int*   dst = (const int*)d_in[2];
    const float* W0  = (const float*)d_in[3];
    const float* b0  = (const float*)d_in[4];
    const float* W1  = (const float*)d_in[5];
    const float* b1  = (const float*)d_in[6];
    const float* Wc  = (const float*)d_in[7];
    const float* bc  = (const float*)d_in[8];
    float* out = (float*)d_out;
    float* out_h = out;                          // [N,128]
    float* out_logits = out + (size_t)NN * HID;  // [N,40]

    float *pCsrc, *pCdst;
    __half *pH, *pH1;
    int *pCntS, *pCntD, *pRow, *pPos, *pBsum, *pEsrc, *pTick;
    cudaGetSymbolAddress((void**)&pCsrc, g_csrc);
    cudaGetSymbolAddress((void**)&pCdst, g_cdst);
    cudaGetSymbolAddress((void**)&pH, g_half);
    cudaGetSymbolAddress((void**)&pH1, g_h1);
    cudaGetSymbolAddress((void**)&pCntS, g_cnt_s);
    cudaGetSymbolAddress((void**)&pCntD, g_cnt_d);
    cudaGetSymbolAddress((void**)&pRow, g_rowptr);
    cudaGetSymbolAddress((void**)&pPos, g_pos);
    cudaGetSymbolAddress((void**)&pBsum, g_bsum);
    cudaGetSymbolAddress((void**)&pEsrc, g_esrc);
    cudaGetSymbolAddress((void**)&pTick, g_tick);

    const int TB = 256;

    // ---- degree norms + CSR build (once; shared by both layers) ----
    zeroi2_kernel<<<(NN + TB - 1) / TB, TB>>>(pCntS, pCntD, pTick, NN);
    deg_kernel<<<(EE + TB - 1) / TB, TB>>>(src, dst, pCntS, pCntD, EE);
    scan_local_kernel<<<NB_SCAN, 256>>>(pCntD, pRow, pBsum, NN);
    scan_bsum_kernel<<<1, 128>>>(pBsum, NB_SCAN);
    scan_add_norm_kernel<<<(NN + TB - 1) / TB, TB>>>(pRow, pPos, pBsum,
                                                     pCntS, pCntD, pCsrc, pCdst, NN);
    fill_kernel<<<(EE + TB - 1) / TB, TB>>>(src, dst, pPos, pEsrc, EE);

    const int nmma = (NN + 127) / 128;       // 782
    const int ncls = (NN + 63) / 64;         // 1563

    // ---- layer 0: h16 = (x @ W0)*c_src; h1(fp16) = relu(agg(h16)*c_dst + b0) ----
    mma_gemm_kernel<FIN, false, true><<<nmma, 256>>>(x, W0, pCsrc, pH, NN);
    agg_half_kernel<true, true><<<AGG_BLOCKS, TB>>>(pH, pEsrc, pRow, pCdst, b0, pH1,
                                                    pTick + 0, NN);

    // ---- layer 1: h16 = (h1 @ W1)*c_src; out_h = agg(h16)*c_dst + b1 ----
    mma_gemm_kernel<HID, true, true><<<nmma, 256>>>(pH1, W1, pCsrc, pH, NN);
    agg_half_kernel<false, false><<<AGG_BLOCKS, TB>>>(pH, pEsrc, pRow, pCdst, b1, out_h,
                                                      pTick + 1, NN);

    // ---- logits = relu(h) @ Wc + bc ----
    classifier_kernel<<<ncls, 320>>>(out_h, Wc, bc, out_logits, NN);
}

// round 16
// speedup vs baseline: 1.0790x; 1.0790x over previous
#include <cuda_runtime.h>
#include <cuda_fp16.h>
#include <cstdint>

#define NN 100000
#define EE 1600000
#define FIN 256
#define HID 128
#define NCLS 40
#define NB_SCAN 98   // ceil(NN/1024)

// ---------------- scratch (device globals; no allocation allowed) ----------------
__device__ float  g_csrc[NN];
__device__ float  g_cdst[NN];
__device__ int    g_cnt_s[NN];
__device__ int    g_cnt_d[NN];
__device__ int    g_rowptr[NN + 1];
__device__ int    g_pos[NN];
__device__ int    g_bsum[128];
__device__ int    g_esrc[EE];
__device__ __half g_half[(size_t)NN * HID];   // fp16 h (gather-side, layer outputs)
__device__ __half g_h1[(size_t)NN * HID];     // fp16 h1 (layer-0 agg out = GEMM-1 in)

// ---------------- mma.sync tf32 helpers (baseline PTX, compiles at compute_103) ---
__device__ __forceinline__ uint32_t f2tf32(float x) {
    uint32_t r;
    asm("cvt.rna.tf32.f32 %0, %1;" : "=r"(r) : "f"(x));
    return r;
}
__device__ __forceinline__ void mma_tf32(float* d, const uint32_t* a, const uint32_t* b) {
    asm volatile(
        "mma.sync.aligned.m16n8k8.row.col.f32.tf32.tf32.f32 "
        "{%0,%1,%2,%3}, {%4,%5,%6,%7}, {%8,%9}, {%0,%1,%2,%3};"
        : "+f"(d[0]), "+f"(d[1]), "+f"(d[2]), "+f"(d[3])
        : "r"(a[0]), "r"(a[1]), "r"(a[2]), "r"(a[3]), "r"(b[0]), "r"(b[1]));
}

// ============ HMMA tf32 GEMM: out[r][c] = (A[r][:] @ W[:][c]) * rowscale[r] ========
// CTA tile 128x128; 8 warps (2x4); warp tile 64x32; K chunked by 32. (R11 version)
template <int K_DIM, bool HALF_IN, bool HALF_OUT>
__global__ void __launch_bounds__(256) mma_gemm_kernel(
    const void* __restrict__ A_v, const float* __restrict__ W,
    const float* __restrict__ rowscale, void* __restrict__ out_v, int n) {
    __shared__ uint32_t sA[128][36];
    __shared__ uint32_t sW[32][136];

    const int t = threadIdx.x;
    const int wid = t >> 5;
    const int lane = t & 31;
    const int g = lane >> 2;      // 0..7
    const int l4 = lane & 3;      // 0..3
    const int warpM = wid >> 2;   // 0..1
    const int warpN = wid & 3;    // 0..3
    const int row0 = blockIdx.x * 128;

    float acc[4][4][4];
#pragma unroll
    for (int mi = 0; mi < 4; mi++)
#pragma unroll
        for (int nj = 0; nj < 4; nj++)
#pragma unroll
            for (int r = 0; r < 4; r++) acc[mi][nj][r] = 0.f;

    for (int k0 = 0; k0 < K_DIM; k0 += 32) {
        // ---- stage A chunk: 128 rows x 32 k -> tf32 ----
#pragma unroll
        for (int i = 0; i < 4; i++) {
            int j4 = t + i * 256;              // 0..1023
            int r = j4 >> 3, kq = j4 & 7;
            int grow = row0 + r;
            float4 v = make_float4(0.f, 0.f, 0.f, 0.f);
            if (grow < n) {
                if (HALF_IN) {
                    const __half* Ah = (const __half*)A_v;
                    int2 p = *reinterpret_cast<const int2*>(Ah + (size_t)grow * K_DIM + k0 + kq * 4);
                    float2 f0 = __half22float2(*reinterpret_cast<__half2*>(&p.x));
                    float2 f1 = __half22float2(*reinterpret_cast<__half2*>(&p.y));
                    v = make_float4(f0.x, f0.y, f1.x, f1.y);
                } else {
                    const float* Af = (const float*)A_v;
                    v = *reinterpret_cast<const float4*>(Af + (size_t)grow * K_DIM + k0 + kq * 4);
                }
            }
            uint4 b = make_uint4(f2tf32(v.x), f2tf32(v.y), f2tf32(v.z), f2tf32(v.w));
            *reinterpret_cast<uint4*>(&sA[r][kq * 4]) = b;
        }
        // ---- stage W chunk: 32 k x 128 n -> tf32 ----
#pragma unroll
        for (int i = 0; i < 4; i++) {
            int j4 = t + i * 256;              // 0..1023
            int kk = j4 >> 5, c4 = j4 & 31;
            float4 v = *reinterpret_cast<const float4*>(W + (size_t)(k0 + kk) * 128 + c4 * 4);
            uint4 b = make_uint4(f2tf32(v.x), f2tf32(v.y), f2tf32(v.z), f2tf32(v.w));
            *reinterpret_cast<uint4*>(&sW[kk][c4 * 4]) = b;
        }
        __syncthreads();
        // ---- 4 k8 steps ----
#pragma unroll
        for (int ks = 0; ks < 4; ks++) {
            const int k = ks * 8;
            uint32_t af[4][4], bf[4][2];
#pragma unroll
            for (int mi = 0; mi < 4; mi++) {
                int m = warpM * 64 + mi * 16 + g;
                af[mi][0] = sA[m][k + l4];
                af[mi][1] = sA[m + 8][k + l4];
                af[mi][2] = sA[m][k + l4 + 4];
                af[mi][3] = sA[m + 8][k + l4 + 4];
            }
#pragma unroll
            for (int nj = 0; nj < 4; nj++) {
                int nb = warpN * 32 + nj * 8 + g;
                bf[nj][0] = sW[k + l4][nb];
                bf[nj][1] = sW[k + l4 + 4][nb];
            }
#pragma unroll
            for (int mi = 0; mi < 4; mi++)
#pragma unroll
                for (int nj = 0; nj < 4; nj++)
                    mma_tf32(acc[mi][nj], af[mi], bf[nj]);
        }
        __syncthreads();
    }

    // ---- epilogue: scale rows, store ----
#pragma unroll
    for (int mi = 0; mi < 4; mi++) {
        int ra = row0 + warpM * 64 + mi * 16 + g;
        int rb = ra + 8;
        float sa = (ra < n) ? rowscale[ra] : 0.f;
        float sb = (rb < n) ? rowscale[rb] : 0.f;
#pragma unroll
        for (int nj = 0; nj < 4; nj++) {
            int col = warpN * 32 + nj * 8 + 2 * l4;
            if (HALF_OUT) {
                __half* o = (__half*)out_v;
                if (ra < n)
                    *reinterpret_cast<__half2*>(o + (size_t)ra * 128 + col) =
                        __floats2half2_rn(acc[mi][nj][0] * sa, acc[mi][nj][1] * sa);
                if (rb < n)
                    *reinterpret_cast<__half2*>(o + (size_t)rb * 128 + col) =
                        __floats2half2_rn(acc[mi][nj][2] * sb, acc[mi][nj][3] * sb);
            } else {
                float* o = (float*)out_v;
                if (ra < n) {
                    float2 v = make_float2(acc[mi][nj][0] * sa, acc[mi][nj][1] * sa);
                    *reinterpret_cast<float2*>(o + (size_t)ra * 128 + col) = v;
                }
                if (rb < n) {
                    float2 v = make_float2(acc[mi][nj][2] * sb, acc[mi][nj][3] * sb);
                    *reinterpret_cast<float2*>(o + (size_t)rb * 128 + col) = v;
                }
            }
        }
    }
}

// ---------------- zero two int arrays in one launch ----------------
__global__ void zeroi2_kernel(int* __restrict__ p0, int* __restrict__ p1, int n) {
    int i = blockIdx.x * blockDim.x + threadIdx.x;
    if (i < n) { p0[i] = 0; p1[i] = 0; }
}

// ---------------- degree histogram (int) ----------------
__global__ void deg_kernel(const int* __restrict__ src, const int* __restrict__ dst,
                           int* __restrict__ cs, int* __restrict__ cd, int e) {
    int i = blockIdx.x * blockDim.x + threadIdx.x;
    if (i < e) {
        atomicAdd(&cs[src[i]], 1);
        atomicAdd(&cd[dst[i]], 1);
    }
}

// ---------------- degree norms (early; unblocks GEMM0 on the side stream) ----------
__global__ void norm_kernel(const int* __restrict__ cs, const int* __restrict__ cd,
                            float* __restrict__ ncs, float* __restrict__ ncd, int n) {
    int i = blockIdx.x * blockDim.x + threadIdx.x;
    if (i < n) {
        ncs[i] = rsqrtf(fmaxf((float)cs[i], 1.f));
        ncd[i] = rsqrtf(fmaxf((float)cd[i], 1.f));
    }
}

// ---------------- scan stage 1 ----------------
__global__ void __launch_bounds__(256) scan_local_kernel(
    const int* __restrict__ in, int* __restrict__ out, int* __restrict__ bsum, int n) {
    __shared__ int wsum[8];
    int t = threadIdx.x;
    int base = blockIdx.x * 1024 + t * 4;
    int v[4];
#pragma unroll
    for (int i = 0; i < 4; i++) v[i] = (base + i < n) ? in[base + i] : 0;
    int tsum = v[0] + v[1] + v[2] + v[3];
    int lane = t & 31, wid = t >> 5;
    int inc = tsum;
#pragma unroll
    for (int off = 1; off < 32; off <<= 1) {
        int tmp = __shfl_up_sync(0xffffffffu, inc, off);
        if (lane >= off) inc += tmp;
    }
    if (lane == 31) wsum[wid] = inc;
    __syncthreads();
    if (t < 8) {
        int ws = wsum[t];
#pragma unroll
        for (int off = 1; off < 8; off <<= 1) {
            int tmp = __shfl_up_sync(0xffu, ws, off);
            if (t >= off) ws += tmp;
        }
        wsum[t] = ws;
    }
    __syncthreads();
    int excl = inc - tsum + (wid > 0 ? wsum[wid - 1] : 0);
    int run = excl;
#pragma unroll
    for (int i = 0; i < 4; i++) {
        if (base + i < n) out[base + i] = run;
        run += v[i];
    }
    if (t == 255) bsum[blockIdx.x] = wsum[7];
}

// ---------------- scan stage 2 ----------------
__global__ void scan_bsum_kernel(int* __restrict__ bsum, int nb) {
    __shared__ int s[128];
    int t = threadIdx.x;
    int v = (t < nb) ? bsum[t] : 0;
    s[t] = v;
    __syncthreads();
    for (int off = 1; off < 128; off <<= 1) {
        int tmp = (t >= off) ? s[t - off] : 0;
        __syncthreads();
        s[t] += tmp;
        __syncthreads();
    }
    if (t < nb) bsum[t] = s[t] - v;
}

// ---------------- scan stage 3 ----------------
__global__ void scan_add_kernel(int* __restrict__ rowptr, int* __restrict__ pos,
                                const int* __restrict__ bsum, int n) {
    int i = blockIdx.x * blockDim.x + threadIdx.x;
    if (i < n) {
        int v = rowptr[i] + bsum[i >> 10];
        rowptr[i] = v;
        pos[i] = v;
    }
    if (i == 0) rowptr[n] = EE;
}

// ---------------- CSR bucket fill ----------------
__global__ void fill_kernel(const int* __restrict__ src, const int* __restrict__ dst,
                            int* __restrict__ pos, int* __restrict__ esrc, int e) {
    int i = blockIdx.x * blockDim.x + threadIdx.x;
    if (i < e) {
        int p = atomicAdd(&pos[dst[i]], 1);
        esrc[p] = src[i];
    }
}

// ------- aggregation v4 (R11 winner): warp/dst, int2/lane, MLP=8 -------------------
template <bool RELU, bool HALF_OUT>
__global__ void __launch_bounds__(256) agg_half_kernel(
    const __half* __restrict__ h, const int* __restrict__ esrc,
    const int* __restrict__ rowptr, const float* __restrict__ cdst,
    const float* __restrict__ bias, void* __restrict__ out_v, int n) {
    int g = blockIdx.x * blockDim.x + threadIdx.x;
    int w = g >> 5;
    int lane = g & 31;
    if (w >= n) return;
    int beg = rowptr[w];
    int end = rowptr[w + 1];
    const int2* hb = reinterpret_cast<const int2*>(h);  // 1 int2 = 4 halfs; 32/row
    float4 acc = make_float4(0.f, 0.f, 0.f, 0.f);
    int e = beg;
    for (; e + 8 <= end; e += 8) {
        int s[8];
#pragma unroll
        for (int q = 0; q < 8; q++) s[q] = __ldg(&esrc[e + q]);
        int2 r[8];
#pragma unroll
        for (int q = 0; q < 8; q++) r[q] = __ldg(&hb[(size_t)s[q] * 32 + lane]);
#pragma unroll
        for (int q = 0; q < 8; q++) {
            float2 a0 = __half22float2(*reinterpret_cast<__half2*>(&r[q].x));
            float2 b0 = __half22float2(*reinterpret_cast<__half2*>(&r[q].y));
            acc.x += a0.x; acc.y += a0.y; acc.z += b0.x; acc.w += b0.y;
        }
    }
    for (; e < end; e++) {
        int s = __ldg(&esrc[e]);
        int2 r0 = __ldg(&hb[(size_t)s * 32 + lane]);
        float2 a0 = __half22float2(*reinterpret_cast<__half2*>(&r0.x));
        float2 b0 = __half22float2(*reinterpret_cast<__half2*>(&r0.y));
        acc.x += a0.x; acc.y += a0.y; acc.z += b0.x; acc.w += b0.y;
    }
    float c = cdst[w];
    float4 b = ((const float4*)bias)[lane];
    float4 r = make_float4(acc.x * c + b.x, acc.y * c + b.y,
                           acc.z * c + b.z, acc.w * c + b.w);
    if (RELU) {
        r.x = fmaxf(r.x, 0.f); r.y = fmaxf(r.y, 0.f);
        r.z = fmaxf(r.z, 0.f); r.w = fmaxf(r.w, 0.f);
    }
    if (HALF_OUT) {
        __half2 h0 = __floats2half2_rn(r.x, r.y);
        __half2 h1 = __floats2half2_rn(r.z, r.w);
        int2 pk;
        pk.x = *reinterpret_cast<int*>(&h0);
        pk.y = *reinterpret_cast<int*>(&h1);
        reinterpret_cast<int2*>(out_v)[(size_t)w * 32 + lane] = pk;
    } else {
        reinterpret_cast<float4*>(out_v)[(size_t)w * 32 + lane] = r;
    }
}

// ---------------- classifier: logits = relu(h) @ Wc + bc ---------------------------
__global__ void __launch_bounds__(320) classifier_kernel(
    const float* __restrict__ h, const float* __restrict__ Wc,
    const float* __restrict__ bc, float* __restrict__ out, int n) {
    __shared__ float Wt[NCLS][132];   // [c][k]
    __shared__ float4 hs4[8][33];     // [r][k4], relu-applied
    __shared__ float bs[NCLS];

    const int t = threadIdx.x;
    for (int j = t; j < 128 * NCLS; j += 320) {
        int k = j / NCLS, c = j % NCLS;
        Wt[c][k] = Wc[j];
    }
    if (t < NCLS) bs[t] = bc[t];

    const int row0 = blockIdx.x * 64;
    const int r = t / NCLS;       // 0..7
    const int c = t % NCLS;       // 0..39
    for (int rr0 = 0; rr0 < 64; rr0 += 8) {
        __syncthreads();
        if (t < 256) {
            int lr = t >> 5, k4 = t & 31;
            int grow = row0 + rr0 + lr;
            float4 v = make_float4(0.f, 0.f, 0.f, 0.f);
            if (grow < n) {
                v = *reinterpret_cast<const float4*>(h + (size_t)grow * 128 + k4 * 4);
                v.x = fmaxf(v.x, 0.f); v.y = fmaxf(v.y, 0.f);
                v.z = fmaxf(v.z, 0.f); v.w = fmaxf(v.w, 0.f);
            }
            hs4[lr][k4] = v;
        }
        __syncthreads();
        float acc = bs[c];
#pragma unroll
        for (int k4 = 0; k4 < 32; k4++) {
            float4 hv = hs4[r][k4];
            float4 wv = *reinterpret_cast<const float4*>(&Wt[c][k4 * 4]);
            acc = fmaf(hv.x, wv.x, acc);
            acc = fmaf(hv.y, wv.y, acc);
            acc = fmaf(hv.z, wv.z, acc);
            acc = fmaf(hv.w, wv.w, acc);
        }
        int grow = row0 + rr0 + r;
        if (grow < n) out[(size_t)grow * NCLS + c] = acc;
    }
}

// ---------------- launch ------------------------------------------------------------
extern "C" void kernel_launch(void* const* d_in, const int* in_sizes, int n_in,
                              void* d_out, int out_size) {
    const float* x   = (const float*)d_in[0];
    const int*   src = (const int*)d_in[1];
    const int*   dst = (const int*)d_in[2];
    const float* W0  = (const float*)d_in[3];
    const float* b0  = (const float*)d_in[4];
    const float* W1  = (const float*)d_in[5];
    const float* b1  = (const float*)d_in[6];
    const float* Wc  = (const float*)d_in[7];
    const float* bc  = (const float*)d_in[8];
    float* out = (float*)d_out;
    float* out_h = out;                          // [N,128]
    float* out_logits = out + (size_t)NN * HID;  // [N,40]

    float *pCsrc, *pCdst;
    __half *pH, *pH1;
    int *pCntS, *pCntD, *pRow, *pPos, *pBsum, *pEsrc;
    cudaGetSymbolAddress((void**)&pCsrc, g_csrc);
    cudaGetSymbolAddress((void**)&pCdst, g_cdst);
    cudaGetSymbolAddress((void**)&pH, g_half);
    cudaGetSymbolAddress((void**)&pH1, g_h1);
    cudaGetSymbolAddress((void**)&pCntS, g_cnt_s);
    cudaGetSymbolAddress((void**)&pCntD, g_cnt_d);
    cudaGetSymbolAddress((void**)&pRow, g_rowptr);
    cudaGetSymbolAddress((void**)&pPos, g_pos);
    cudaGetSymbolAddress((void**)&pBsum, g_bsum);
    cudaGetSymbolAddress((void**)&pEsrc, g_esrc);

    // side stream + events, created once on the first (uncaptured) call; on
    // captured calls only event record/wait APIs run (graph-legal fork/join).
    static cudaStream_t s_side = nullptr;
    static cudaEvent_t ev_norm = nullptr, ev_g0 = nullptr;
    if (s_side == nullptr) {
        cudaStreamCreateWithFlags(&s_side, cudaStreamNonBlocking);
        cudaEventCreateWithFlags(&ev_norm, cudaEventDisableTiming);
        cudaEventCreateWithFlags(&ev_g0, cudaEventDisableTiming);
    }

    const int TB = 256;
    const int nmma = (NN + 127) / 128;       // 782
    const int nagg = (NN * 32 + TB - 1) / TB;
    const int ncls = (NN + 63) / 64;         // 1563

    // ---- degrees + norms (needed by GEMM0 epilogue) ----
    zeroi2_kernel<<<(NN + TB - 1) / TB, TB>>>(pCntS, pCntD, NN);
    deg_kernel<<<(EE + TB - 1) / TB, TB>>>(src, dst, pCntS, pCntD, EE);
    norm_kernel<<<(NN + TB - 1) / TB, TB>>>(pCntS, pCntD, pCsrc, pCdst, NN);

    // ---- fork: GEMM0 on side stream, CSR build on main stream ----
    cudaEventRecord(ev_norm, 0);
    cudaStreamWaitEvent(s_side, ev_norm, 0);
    mma_gemm_kernel<FIN, false, true><<<nmma, 256, 0, s_side>>>(x, W0, pCsrc, pH, NN);
    cudaEventRecord(ev_g0, s_side);

    scan_local_kernel<<<NB_SCAN, 256>>>(pCntD, pRow, pBsum, NN);
    scan_bsum_kernel<<<1, 128>>>(pBsum, NB_SCAN);
    scan_add_kernel<<<(NN + TB - 1) / TB, TB>>>(pRow, pPos, pBsum, NN);
    fill_kernel<<<(EE + TB - 1) / TB, TB>>>(src, dst, pPos, pEsrc, EE);

    // ---- join: agg0 needs both GEMM0 output and CSR ----
    cudaStreamWaitEvent(0, ev_g0, 0);

    // ---- layer 0 agg: h1(fp16) = relu(agg(h16)*c_dst + b0) ----
    agg_half_kernel<true, true><<<nagg, TB>>>(pH, pEsrc, pRow, pCdst, b0, pH1, NN);

    // ---- layer 1: h16 = (h1 @ W1)*c_src; out_h = agg(h16)*c_dst + b1 ----
    mma_gemm_kernel<HID, true, true><<<nmma, 256>>>(pH1, W1, pCsrc, pH, NN);
    agg_half_kernel<false, false><<<nagg, TB>>>(pH, pEsrc, pRow, pCdst, b1, out_h, NN);

    // ---- logits = relu(h) @ Wc + bc ----
    classifier_kernel<<<ncls, 320>>>(out_h, Wc, bc, out_logits, NN);
}